// round 16
// baseline (speedup 1.0000x reference)
#include <cuda_runtime.h>
#include <cuda_fp16.h>
#include <math.h>
#include <stdint.h>

#define T   2048
#define H   1024
#define FF  3584
#define NE  8
#define TK  2

#define BM   128
#define BK   64
#define NI1  (H / BK)    // 16
#define NI2  (FF / BK)   // 56
#define NT1  (2*FF/128)  // 56
#define NT2  (H/128)     // 8
#define SMEMSZ 98304     // 3 stages x 32KB

// ---- scratch (fp16 fragment-major blobs of 16KB = 1024 uint4) ----
__device__ __align__(16) uint4 d_xp [(size_t)NE * 16 * NI1 * 1024];
__device__ __align__(16) uint4 d_ap [(size_t)NE * 16 * NI2 * 1024];
__device__ __align__(16) uint4 d_wp1[(size_t)NE * NT1 * NI1 * 1024];
__device__ __align__(16) uint4 d_wp2[(size_t)NE * NT2 * NI2 * 1024];
__device__ int   d_slot_token[NE * T];   // fixed per-expert segments of capacity T
__device__ float d_slot_w[NE * T];
__device__ int   d_counts[NE];

// ===================== helpers =====================
__device__ __forceinline__ uint32_t pk2(float lo, float hi) {
    __half2 h = __floats2half2_rn(lo, hi);
    return *(uint32_t*)&h;
}
__device__ __forceinline__ void mma_fp16(float* c, uint32_t a0, uint32_t a1,
                                         uint32_t a2, uint32_t a3,
                                         uint32_t b0, uint32_t b1) {
    asm volatile(
        "mma.sync.aligned.m16n8k16.row.col.f32.f16.f16.f32 "
        "{%0,%1,%2,%3}, {%4,%5,%6,%7}, {%8,%9}, {%0,%1,%2,%3};\n"
        : "+f"(c[0]), "+f"(c[1]), "+f"(c[2]), "+f"(c[3])
        : "r"(a0), "r"(a1), "r"(a2), "r"(a3), "r"(b0), "r"(b1));
}
__device__ __forceinline__ uint32_t s2u(const void* p) {
    uint32_t a;
    asm("{ .reg .u64 t; cvta.to.shared.u64 t, %1; cvt.u32.u64 %0, t; }"
        : "=r"(a) : "l"(p));
    return a;
}
// A staging: L2-only (blobs differ between co-resident CTAs; keep L1 clean)
__device__ __forceinline__ void cpa16(uint32_t saddr, const void* gptr) {
    asm volatile("cp.async.cg.shared.global [%0], [%1], 16;" :: "r"(saddr), "l"(gptr));
}
// B staging: L1-allocating — co-resident CTA (adjacent blockIdx.x) reads the
// SAME B blob nearly in lockstep and hits L1, halving B's L2 traffic.
__device__ __forceinline__ void cpa16_ca(uint32_t saddr, const void* gptr) {
    asm volatile("cp.async.ca.shared.global [%0], [%1], 16;" :: "r"(saddr), "l"(gptr));
}
__device__ __forceinline__ void cpa_commit() {
    asm volatile("cp.async.commit_group;" ::: "memory");
}
__device__ __forceinline__ void cpa_wait1() {
    asm volatile("cp.async.wait_group 1;" ::: "memory");
}
__device__ __forceinline__ void cpa_wait0() {
    asm volatile("cp.async.wait_group 0;" ::: "memory");
}
__device__ __forceinline__ uint4 lds128(const char* p) { return *(const uint4*)p; }
__device__ __forceinline__ float silu(float g) { return g / (1.f + expf(-g)); }

// ===================== zero counts =====================
__global__ void zero_counts_kernel() {
    if (threadIdx.x < NE) d_counts[threadIdx.x] = 0;
}

// ===================== zero out (runs on side stream; gemm2 is the consumer) =====
__global__ void zero_out_kernel(float* __restrict__ out) {
    int idx = blockIdx.x * blockDim.x + threadIdx.x;
    float4 z4 = make_float4(0.f, 0.f, 0.f, 0.f);
    if (idx < T * H / 4) ((float4*)out)[idx] = z4;
}

// ===================== router: logits + top2 + inline scatter =====
__global__ void router_kernel(const float* __restrict__ x,
                              const float* __restrict__ gw,
                              float* __restrict__ logits, int write_logits)
{
    int warp = (blockIdx.x * blockDim.x + threadIdx.x) >> 5;
    int lane = threadIdx.x & 31;
    if (warp >= T) return;

    const float* xr = x + (size_t)warp * H;
    float acc[NE];
#pragma unroll
    for (int e = 0; e < NE; e++) acc[e] = 0.f;
    for (int i = lane; i < H; i += 32) {
        float xv = xr[i];
#pragma unroll
        for (int e = 0; e < NE; e++) acc[e] += xv * gw[e * H + i];
    }
#pragma unroll
    for (int e = 0; e < NE; e++) {
#pragma unroll
        for (int off = 16; off > 0; off >>= 1)
            acc[e] += __shfl_xor_sync(0xffffffffu, acc[e], off);
    }
    if (lane == 0) {
        if (write_logits) {
#pragma unroll
            for (int e = 0; e < NE; e++) logits[warp * NE + e] = acc[e];
        }
        int i0 = 0;
#pragma unroll
        for (int e = 1; e < NE; e++) if (acc[e] > acc[i0]) i0 = e;
        int i1 = (i0 == 0) ? 1 : 0;
#pragma unroll
        for (int e = 0; e < NE; e++)
            if (e != i0 && acc[e] > acc[i1]) i1 = e;
        float m  = fmaxf(acc[i0], acc[i1]);
        float p0 = expf(acc[i0] - m), p1 = expf(acc[i1] - m);
        float inv = 1.f / (p0 + p1);
        int q0 = atomicAdd(&d_counts[i0], 1);
        d_slot_token[i0 * T + q0] = warp;
        d_slot_w[i0 * T + q0]     = p0 * inv;
        int q1 = atomicAdd(&d_counts[i1], 1);
        d_slot_token[i1 * T + q1] = warp;
        d_slot_w[i1 * T + q1]     = p1 * inv;
    }
}

// ===================== A packer (gemm1 input) =====================
__global__ __launch_bounds__(256) void pack_x_kernel(const float* __restrict__ x)
{
    int e  = blockIdx.z, mt = blockIdx.y, kt = blockIdx.x;
    int cnt = d_counts[e];
    int m0  = mt * BM;
    if (m0 >= cnt) return;
    int seg = e * T;

    __shared__ int stok[BM];
    int t = threadIdx.x;
    if (t < BM) {
        int m = m0 + t;
        stok[t] = d_slot_token[seg + (m < cnt ? m : cnt - 1)];
    }
    __syncthreads();

    uint4* dst = d_xp + ((size_t)(e * 16 + mt) * NI1 + kt) * 1024;
#pragma unroll
    for (int i = 0; i < 4; i++) {
        int idx = i * 256 + t;
        int grp = idx >> 5, l = idx & 31;
        int tm = grp >> 2, tk = grp & 3;
        int mlo = tm * 16 + (l >> 2);
        int kb  = kt * 64 + tk * 16 + 2 * (l & 3);
        const float* rlo = x + (size_t)stok[mlo] * H + kb;
        const float* rhi = x + (size_t)stok[mlo + 8] * H + kb;
        float2 p0 = *(const float2*)(rlo);
        float2 p1 = *(const float2*)(rhi);
        float2 p2 = *(const float2*)(rlo + 8);
        float2 p3 = *(const float2*)(rhi + 8);
        dst[idx] = make_uint4(pk2(p0.x, p0.y), pk2(p1.x, p1.y),
                              pk2(p2.x, p2.y), pk2(p3.x, p3.y));
    }
}

// ===================== W packers =====================
template <bool IS1>
__global__ __launch_bounds__(256) void pack_w_kernel(const float* __restrict__ W)
{
    constexpr int KTOT = IS1 ? H : FF;
    constexpr int NB   = IS1 ? (2 * FF) : H;
    constexpr int NI   = IS1 ? NI1 : NI2;
    constexpr int NT   = IS1 ? NT1 : NT2;

    int e = blockIdx.z, nt = blockIdx.y, kt = blockIdx.x;
    int t = threadIdx.x;

    uint4* dst = (IS1 ? d_wp1 : d_wp2) + ((size_t)(e * NT + nt) * NI + kt) * 1024;
    const float* Wb = W + (size_t)e * KTOT * NB;

#pragma unroll
    for (int i = 0; i < 4; i++) {
        int idx = i * 256 + t;
        int g2 = idx >> 5, l = idx & 31;
        int tn, tkp, n;
        if (IS1) {
            int which = g2 >> 4, gi = g2 & 15;
            tn = gi >> 1;  tkp = gi & 1;
            n = which * FF + nt * 64 + tn * 8 + (l >> 2);
        } else {
            tn = g2 >> 1;  tkp = g2 & 1;
            n = nt * 128 + tn * 8 + (l >> 2);
        }
        size_t kA = (size_t)(kt * 64 + tkp * 32 + 2 * (l & 3));
        size_t kB = kA + 16;
        dst[idx] = make_uint4(
            pk2(Wb[(kA    ) * NB + n], Wb[(kA + 1) * NB + n]),
            pk2(Wb[(kA + 8) * NB + n], Wb[(kA + 9) * NB + n]),
            pk2(Wb[(kB    ) * NB + n], Wb[(kB + 1) * NB + n]),
            pk2(Wb[(kB + 8) * NB + n], Wb[(kB + 9) * NB + n]));
    }
}

// ===================== GEMM (fp16 m16n8k16, BK=64, 3-stage cp.async) =====================
// IS1: tile 128m x (64g|64u); epilogue writes d_ap blob (lane-identity).
// !IS1: tile 128m x 128n; epilogue atomicAdd into out[token].
template <bool IS1>
__global__ __launch_bounds__(256, 2)
void moe_gemm_mma(float* __restrict__ out)
{
    constexpr int NI = IS1 ? NI1 : NI2;
    constexpr int NT = IS1 ? NT1 : NT2;
    constexpr uint32_t STG = 32768;

    int e   = blockIdx.z;
    int cnt = d_counts[e];
    int m0  = blockIdx.x * BM;
    if (m0 >= cnt) return;
    int seg = e * T;

    extern __shared__ __align__(16) char smem[];
    uint32_t smem_u = s2u(smem);

    int t = threadIdx.x, w = t >> 5, lane = t & 31;
    int g = lane >> 2, tig = lane & 3;

    const uint4* aBase = (IS1 ? d_xp : d_ap) + ((size_t)(e * 16 + blockIdx.x) * NI) * 1024;
    const uint4* bBase = (IS1 ? d_wp1 : d_wp2) + ((size_t)(e * NT + blockIdx.y) * NI) * 1024;

    constexpr int MT    = IS1 ? 2 : 4;
    constexpr int NSETS = IS1 ? 2 : 1;
    int mw = IS1 ? (w >> 1) : (w >> 2);
    int nw = IS1 ? (w & 1)  : (w & 3);

    uint32_t abase[MT];
#pragma unroll
    for (int mt = 0; mt < MT; mt++)
        abase[mt] = (uint32_t)(((mw * MT + mt) * 4) * 512 + lane * 16);
    uint32_t bbase[NSETS][4];
#pragma unroll
    for (int s = 0; s < NSETS; s++)
#pragma unroll
        for (int nt = 0; nt < 4; nt++) {
            int tn = nw * 4 + nt;
            bbase[s][nt] = (uint32_t)(16384 + (s * 16 + tn * 2) * 512 + lane * 16);
        }

    float acc[NSETS][MT][4][4];
#pragma unroll
    for (int s = 0; s < NSETS; s++)
#pragma unroll
        for (int mt = 0; mt < MT; mt++)
#pragma unroll
            for (int nt = 0; nt < 4; nt++)
#pragma unroll
                for (int q = 0; q < 4; q++) acc[s][mt][nt][q] = 0.f;

    // ---------- prologue ----------
#pragma unroll
    for (int p = 0; p < 2; p++) {
        uint32_t sb = p * STG;
        const char* aSrc = (const char*)(aBase + (size_t)p * 1024);
        const char* bSrc = (const char*)(bBase + (size_t)p * 1024);
#pragma unroll
        for (int i = 0; i < 4; i++) {
            cpa16   (smem_u + sb + t * 16 + i * 4096,          aSrc + t * 16 + i * 4096);
            cpa16_ca(smem_u + sb + 16384 + t * 16 + i * 4096,  bSrc + t * 16 + i * 4096);
        }
        cpa_commit();
    }

    // ---------- mainloop ----------
    uint32_t sb = 0;
    for (int it = 0; it < NI; it++) {
        if (it == NI - 1) cpa_wait0(); else cpa_wait1();
        __syncthreads();
        if (it + 2 < NI) {
            uint32_t nb = sb + 2 * STG;
            if (nb >= 3 * STG) nb -= 3 * STG;
            const char* aSrc = (const char*)(aBase + (size_t)(it + 2) * 1024);
            const char* bSrc = (const char*)(bBase + (size_t)(it + 2) * 1024);
#pragma unroll
            for (int i = 0; i < 4; i++) {
                cpa16   (smem_u + nb + t * 16 + i * 4096,          aSrc + t * 16 + i * 4096);
                cpa16_ca(smem_u + nb + 16384 + t * 16 + i * 4096,  bSrc + t * 16 + i * 4096);
            }
            cpa_commit();
        }
        const char* sm = smem + sb;
        uint4 bfr[NSETS][4];
#pragma unroll
        for (int ks = 0; ks < 4; ks++) {
            if ((ks & 1) == 0) {
                uint32_t tkpoff = (uint32_t)((ks >> 1) * 512);
#pragma unroll
                for (int s = 0; s < NSETS; s++)
#pragma unroll
                    for (int nt = 0; nt < 4; nt++)
                        bfr[s][nt] = lds128(sm + bbase[s][nt] + tkpoff);
            }
#pragma unroll
            for (int mt = 0; mt < MT; mt++) {
                uint4 af = lds128(sm + abase[mt] + (uint32_t)(ks * 512));
#pragma unroll
                for (int s = 0; s < NSETS; s++)
#pragma unroll
                    for (int nt = 0; nt < 4; nt++) {
                        uint32_t b0 = (ks & 1) ? bfr[s][nt].z : bfr[s][nt].x;
                        uint32_t b1 = (ks & 1) ? bfr[s][nt].w : bfr[s][nt].y;
                        mma_fp16(acc[s][mt][nt], af.x, af.y, af.z, af.w, b0, b1);
                    }
            }
        }
        sb += STG;
        if (sb >= 3 * STG) sb = 0;
    }

    // ---------- epilogue ----------
    if (IS1) {
        uint4* blob = d_ap + ((size_t)(e * 16 + blockIdx.x) * NI2 + blockIdx.y) * 1024;
#pragma unroll
        for (int mt = 0; mt < MT; mt++) {
            int mlo = mw * 32 + mt * 16 + g;
            float wlo = d_slot_w[seg + min(m0 + mlo,     cnt - 1)];
            float whi = d_slot_w[seg + min(m0 + mlo + 8, cnt - 1)];
#pragma unroll
            for (int tb = 0; tb < 2; tb++) {
                int na = tb * 2, nb2 = tb * 2 + 1;
                float l0 = silu(acc[0][mt][na ][0]) * acc[1][mt][na ][0] * wlo;
                float l1 = silu(acc[0][mt][na ][1]) * acc[1][mt][na ][1] * wlo;
                float h0 = silu(acc[0][mt][na ][2]) * acc[1][mt][na ][2] * whi;
                float h1 = silu(acc[0][mt][na ][3]) * acc[1][mt][na ][3] * whi;
                float l2 = silu(acc[0][mt][nb2][0]) * acc[1][mt][nb2][0] * wlo;
                float l3 = silu(acc[0][mt][nb2][1]) * acc[1][mt][nb2][1] * wlo;
                float h2 = silu(acc[0][mt][nb2][2]) * acc[1][mt][nb2][2] * whi;
                float h3 = silu(acc[0][mt][nb2][3]) * acc[1][mt][nb2][3] * whi;
                int grp = (mw * 2 + mt) * 4 + 2 * nw + tb;
                blob[grp * 32 + lane] = make_uint4(pk2(l0, l1), pk2(h0, h1),
                                                   pk2(l2, l3), pk2(h2, h3));
            }
        }
    } else {
        int n0 = blockIdx.y * 128 + nw * 32;
#pragma unroll
        for (int mt = 0; mt < MT; mt++) {
#pragma unroll
            for (int rs = 0; rs < 2; rs++) {
                int m = m0 + mw * 64 + mt * 16 + g + rs * 8;
                if (m < cnt) {
                    int tok = d_slot_token[seg + m];
                    float* row = out + (size_t)tok * H + n0;
#pragma unroll
                    for (int nt = 0; nt < 4; nt++) {
                        atomicAdd(&row[nt * 8 + 2 * tig],     acc[0][mt][nt][rs * 2 + 0]);
                        atomicAdd(&row[nt * 8 + 2 * tig + 1], acc[0][mt][nt][rs * 2 + 1]);
                    }
                }
            }
        }
    }
}

// ===================== launch =====================
extern "C" void kernel_launch(void* const* d_in, const int* in_sizes, int n_in,
                              void* d_out, int out_size)
{
    const float* x   = (const float*)d_in[0];   // [2,1024,1024]
    const float* gw  = (const float*)d_in[1];   // [8,1024]
    const float* wgu = (const float*)d_in[2];   // [8,1024,7168]
    const float* wdn = (const float*)d_in[3];   // [8,3584,1024]
    float* out = (float*)d_out;

    int write_logits = (out_size >= T * H + T * NE) ? 1 : 0;
    float* logits = out + (size_t)T * H;

    cudaFuncSetAttribute(moe_gemm_mma<true>,
                         cudaFuncAttributeMaxDynamicSharedMemorySize, SMEMSZ);
    cudaFuncSetAttribute(moe_gemm_mma<false>,
                         cudaFuncAttributeMaxDynamicSharedMemorySize, SMEMSZ);

    // R13/R15 fork/join shape (measured best).
    cudaStream_t side;
    cudaStreamCreateWithFlags(&side, cudaStreamNonBlocking);
    cudaEvent_t evFork, evW1, evW2;
    cudaEventCreateWithFlags(&evFork, cudaEventDisableTiming);
    cudaEventCreateWithFlags(&evW1,   cudaEventDisableTiming);
    cudaEventCreateWithFlags(&evW2,   cudaEventDisableTiming);

    cudaEventRecord(evFork, 0);
    cudaStreamWaitEvent(side, evFork, 0);

    // side branch: weight packs + out zeroing
    pack_w_kernel<true><<<dim3(NI1, NT1, NE), 256, 0, side>>>(wgu);
    cudaEventRecord(evW1, side);
    zero_out_kernel<<<(T * H / 4 + 255) / 256, 256, 0, side>>>(out);
    pack_w_kernel<false><<<dim3(NI2, NT2, NE), 256, 0, side>>>(wdn);
    cudaEventRecord(evW2, side);

    // main branch: routing chain (scatter inlined in router)
    zero_counts_kernel<<<1, 32>>>();
    router_kernel<<<(T * 32 + 255) / 256, 256>>>(x, gw, logits, write_logits);
    pack_x_kernel<<<dim3(NI1, 16, NE), 256>>>(x);

    cudaStreamWaitEvent(0, evW1, 0);
    moe_gemm_mma<true><<<dim3(16, NT1, NE), 256, SMEMSZ>>>(nullptr);   // (16, 56, 8)
    cudaStreamWaitEvent(0, evW2, 0);
    moe_gemm_mma<false><<<dim3(16, NT2, NE), 256, SMEMSZ>>>(out);      // (16, 8, 8)
}

// round 17
// speedup vs baseline: 1.0897x; 1.0897x over previous
#include <cuda_runtime.h>
#include <cuda_fp16.h>
#include <math.h>
#include <stdint.h>

#define T   2048
#define H   1024
#define FF  3584
#define NE  8
#define TK  2

#define BM   128
#define BK   64
#define NI1  (H / BK)    // 16
#define NI2  (FF / BK)   // 56
#define NT1  (2*FF/128)  // 56
#define NT2  (H/128)     // 8
#define SMEMSZ 98304     // 3 stages x 32KB

// ---- scratch (fp16 fragment-major blobs of 16KB = 1024 uint4) ----
__device__ __align__(16) uint4 d_xp [(size_t)NE * 16 * NI1 * 1024];
__device__ __align__(16) uint4 d_ap [(size_t)NE * 16 * NI2 * 1024];
__device__ __align__(16) uint4 d_wp1[(size_t)NE * NT1 * NI1 * 1024];
__device__ __align__(16) uint4 d_wp2[(size_t)NE * NT2 * NI2 * 1024];
__device__ int   d_slot_token[NE * T];   // fixed per-expert segments of capacity T
__device__ float d_slot_w[NE * T];
__device__ int   d_counts[NE];

// ===================== helpers =====================
__device__ __forceinline__ uint32_t pk2(float lo, float hi) {
    __half2 h = __floats2half2_rn(lo, hi);
    return *(uint32_t*)&h;
}
__device__ __forceinline__ void mma_fp16(float* c, uint32_t a0, uint32_t a1,
                                         uint32_t a2, uint32_t a3,
                                         uint32_t b0, uint32_t b1) {
    asm volatile(
        "mma.sync.aligned.m16n8k16.row.col.f32.f16.f16.f32 "
        "{%0,%1,%2,%3}, {%4,%5,%6,%7}, {%8,%9}, {%0,%1,%2,%3};\n"
        : "+f"(c[0]), "+f"(c[1]), "+f"(c[2]), "+f"(c[3])
        : "r"(a0), "r"(a1), "r"(a2), "r"(a3), "r"(b0), "r"(b1));
}
__device__ __forceinline__ uint32_t s2u(const void* p) {
    uint32_t a;
    asm("{ .reg .u64 t; cvta.to.shared.u64 t, %1; cvt.u32.u64 %0, t; }"
        : "=r"(a) : "l"(p));
    return a;
}
__device__ __forceinline__ void cpa16(uint32_t saddr, const void* gptr) {
    asm volatile("cp.async.cg.shared.global [%0], [%1], 16;" :: "r"(saddr), "l"(gptr));
}
__device__ __forceinline__ void cpa_commit() {
    asm volatile("cp.async.commit_group;" ::: "memory");
}
__device__ __forceinline__ void cpa_wait1() {
    asm volatile("cp.async.wait_group 1;" ::: "memory");
}
__device__ __forceinline__ void cpa_wait0() {
    asm volatile("cp.async.wait_group 0;" ::: "memory");
}
__device__ __forceinline__ uint4 lds128(const char* p) { return *(const uint4*)p; }
__device__ __forceinline__ float silu(float g) { return g / (1.f + expf(-g)); }
// vector reduction: one RED op adds 2 adjacent floats (no return)
__device__ __forceinline__ void red2(float* addr, float a, float b) {
    asm volatile("red.global.add.v2.f32 [%0], {%1, %2};"
                 :: "l"(addr), "f"(a), "f"(b) : "memory");
}

// ===================== zero counts =====================
__global__ void zero_counts_kernel() {
    if (threadIdx.x < NE) d_counts[threadIdx.x] = 0;
}

// ===================== zero out (runs on side stream; gemm2 is the consumer) =====
__global__ void zero_out_kernel(float* __restrict__ out) {
    int idx = blockIdx.x * blockDim.x + threadIdx.x;
    float4 z4 = make_float4(0.f, 0.f, 0.f, 0.f);
    if (idx < T * H / 4) ((float4*)out)[idx] = z4;
}

// ===================== router: logits + top2 + inline scatter =====
__global__ void router_kernel(const float* __restrict__ x,
                              const float* __restrict__ gw,
                              float* __restrict__ logits, int write_logits)
{
    int warp = (blockIdx.x * blockDim.x + threadIdx.x) >> 5;
    int lane = threadIdx.x & 31;
    if (warp >= T) return;

    const float* xr = x + (size_t)warp * H;
    float acc[NE];
#pragma unroll
    for (int e = 0; e < NE; e++) acc[e] = 0.f;
    for (int i = lane; i < H; i += 32) {
        float xv = xr[i];
#pragma unroll
        for (int e = 0; e < NE; e++) acc[e] += xv * gw[e * H + i];
    }
#pragma unroll
    for (int e = 0; e < NE; e++) {
#pragma unroll
        for (int off = 16; off > 0; off >>= 1)
            acc[e] += __shfl_xor_sync(0xffffffffu, acc[e], off);
    }
    if (lane == 0) {
        if (write_logits) {
#pragma unroll
            for (int e = 0; e < NE; e++) logits[warp * NE + e] = acc[e];
        }
        int i0 = 0;
#pragma unroll
        for (int e = 1; e < NE; e++) if (acc[e] > acc[i0]) i0 = e;
        int i1 = (i0 == 0) ? 1 : 0;
#pragma unroll
        for (int e = 0; e < NE; e++)
            if (e != i0 && acc[e] > acc[i1]) i1 = e;
        float m  = fmaxf(acc[i0], acc[i1]);
        float p0 = expf(acc[i0] - m), p1 = expf(acc[i1] - m);
        float inv = 1.f / (p0 + p1);
        int q0 = atomicAdd(&d_counts[i0], 1);
        d_slot_token[i0 * T + q0] = warp;
        d_slot_w[i0 * T + q0]     = p0 * inv;
        int q1 = atomicAdd(&d_counts[i1], 1);
        d_slot_token[i1 * T + q1] = warp;
        d_slot_w[i1 * T + q1]     = p1 * inv;
    }
}

// ===================== A packer (gemm1 input) =====================
__global__ __launch_bounds__(256) void pack_x_kernel(const float* __restrict__ x)
{
    int e  = blockIdx.z, mt = blockIdx.y, kt = blockIdx.x;
    int cnt = d_counts[e];
    int m0  = mt * BM;
    if (m0 >= cnt) return;
    int seg = e * T;

    __shared__ int stok[BM];
    int t = threadIdx.x;
    if (t < BM) {
        int m = m0 + t;
        stok[t] = d_slot_token[seg + (m < cnt ? m : cnt - 1)];
    }
    __syncthreads();

    uint4* dst = d_xp + ((size_t)(e * 16 + mt) * NI1 + kt) * 1024;
#pragma unroll
    for (int i = 0; i < 4; i++) {
        int idx = i * 256 + t;
        int grp = idx >> 5, l = idx & 31;
        int tm = grp >> 2, tk = grp & 3;
        int mlo = tm * 16 + (l >> 2);
        int kb  = kt * 64 + tk * 16 + 2 * (l & 3);
        const float* rlo = x + (size_t)stok[mlo] * H + kb;
        const float* rhi = x + (size_t)stok[mlo + 8] * H + kb;
        float2 p0 = *(const float2*)(rlo);
        float2 p1 = *(const float2*)(rhi);
        float2 p2 = *(const float2*)(rlo + 8);
        float2 p3 = *(const float2*)(rhi + 8);
        dst[idx] = make_uint4(pk2(p0.x, p0.y), pk2(p1.x, p1.y),
                              pk2(p2.x, p2.y), pk2(p3.x, p3.y));
    }
}

// ===================== W packers =====================
template <bool IS1>
__global__ __launch_bounds__(256) void pack_w_kernel(const float* __restrict__ W)
{
    constexpr int KTOT = IS1 ? H : FF;
    constexpr int NB   = IS1 ? (2 * FF) : H;
    constexpr int NI   = IS1 ? NI1 : NI2;
    constexpr int NT   = IS1 ? NT1 : NT2;

    int e = blockIdx.z, nt = blockIdx.y, kt = blockIdx.x;
    int t = threadIdx.x;

    uint4* dst = (IS1 ? d_wp1 : d_wp2) + ((size_t)(e * NT + nt) * NI + kt) * 1024;
    const float* Wb = W + (size_t)e * KTOT * NB;

#pragma unroll
    for (int i = 0; i < 4; i++) {
        int idx = i * 256 + t;
        int g2 = idx >> 5, l = idx & 31;
        int tn, tkp, n;
        if (IS1) {
            int which = g2 >> 4, gi = g2 & 15;
            tn = gi >> 1;  tkp = gi & 1;
            n = which * FF + nt * 64 + tn * 8 + (l >> 2);
        } else {
            tn = g2 >> 1;  tkp = g2 & 1;
            n = nt * 128 + tn * 8 + (l >> 2);
        }
        size_t kA = (size_t)(kt * 64 + tkp * 32 + 2 * (l & 3));
        size_t kB = kA + 16;
        dst[idx] = make_uint4(
            pk2(Wb[(kA    ) * NB + n], Wb[(kA + 1) * NB + n]),
            pk2(Wb[(kA + 8) * NB + n], Wb[(kA + 9) * NB + n]),
            pk2(Wb[(kB    ) * NB + n], Wb[(kB + 1) * NB + n]),
            pk2(Wb[(kB + 8) * NB + n], Wb[(kB + 9) * NB + n]));
    }
}

// ===================== GEMM (fp16 m16n8k16, BK=64, 3-stage cp.async) =====================
// IS1: tile 128m x (64g|64u); epilogue writes d_ap blob (lane-identity).
// !IS1: tile 128m x 128n; epilogue vector-RED into out[token].
template <bool IS1>
__global__ __launch_bounds__(256, 2)
void moe_gemm_mma(float* __restrict__ out)
{
    constexpr int NI = IS1 ? NI1 : NI2;
    constexpr int NT = IS1 ? NT1 : NT2;
    constexpr uint32_t STG = 32768;

    int e   = blockIdx.z;
    int cnt = d_counts[e];
    int m0  = blockIdx.x * BM;
    if (m0 >= cnt) return;
    int seg = e * T;

    extern __shared__ __align__(16) char smem[];
    uint32_t smem_u = s2u(smem);

    int t = threadIdx.x, w = t >> 5, lane = t & 31;
    int g = lane >> 2, tig = lane & 3;

    const uint4* aBase = (IS1 ? d_xp : d_ap) + ((size_t)(e * 16 + blockIdx.x) * NI) * 1024;
    const uint4* bBase = (IS1 ? d_wp1 : d_wp2) + ((size_t)(e * NT + blockIdx.y) * NI) * 1024;

    constexpr int MT    = IS1 ? 2 : 4;
    constexpr int NSETS = IS1 ? 2 : 1;
    int mw = IS1 ? (w >> 1) : (w >> 2);
    int nw = IS1 ? (w & 1)  : (w & 3);

    uint32_t abase[MT];
#pragma unroll
    for (int mt = 0; mt < MT; mt++)
        abase[mt] = (uint32_t)(((mw * MT + mt) * 4) * 512 + lane * 16);
    uint32_t bbase[NSETS][4];
#pragma unroll
    for (int s = 0; s < NSETS; s++)
#pragma unroll
        for (int nt = 0; nt < 4; nt++) {
            int tn = nw * 4 + nt;
            bbase[s][nt] = (uint32_t)(16384 + (s * 16 + tn * 2) * 512 + lane * 16);
        }

    float acc[NSETS][MT][4][4];
#pragma unroll
    for (int s = 0; s < NSETS; s++)
#pragma unroll
        for (int mt = 0; mt < MT; mt++)
#pragma unroll
            for (int nt = 0; nt < 4; nt++)
#pragma unroll
                for (int q = 0; q < 4; q++) acc[s][mt][nt][q] = 0.f;

    // ---------- prologue ----------
#pragma unroll
    for (int p = 0; p < 2; p++) {
        uint32_t sb = p * STG;
        const char* aSrc = (const char*)(aBase + (size_t)p * 1024);
        const char* bSrc = (const char*)(bBase + (size_t)p * 1024);
#pragma unroll
        for (int i = 0; i < 4; i++) {
            cpa16(smem_u + sb + t * 16 + i * 4096,          aSrc + t * 16 + i * 4096);
            cpa16(smem_u + sb + 16384 + t * 16 + i * 4096,  bSrc + t * 16 + i * 4096);
        }
        cpa_commit();
    }

    // ---------- mainloop ----------
    uint32_t sb = 0;
    for (int it = 0; it < NI; it++) {
        if (it == NI - 1) cpa_wait0(); else cpa_wait1();
        __syncthreads();
        if (it + 2 < NI) {
            uint32_t nb = sb + 2 * STG;
            if (nb >= 3 * STG) nb -= 3 * STG;
            const char* aSrc = (const char*)(aBase + (size_t)(it + 2) * 1024);
            const char* bSrc = (const char*)(bBase + (size_t)(it + 2) * 1024);
#pragma unroll
            for (int i = 0; i < 4; i++) {
                cpa16(smem_u + nb + t * 16 + i * 4096,          aSrc + t * 16 + i * 4096);
                cpa16(smem_u + nb + 16384 + t * 16 + i * 4096,  bSrc + t * 16 + i * 4096);
            }
            cpa_commit();
        }
        const char* sm = smem + sb;
        uint4 bfr[NSETS][4];
#pragma unroll
        for (int ks = 0; ks < 4; ks++) {
            if ((ks & 1) == 0) {
                uint32_t tkpoff = (uint32_t)((ks >> 1) * 512);
#pragma unroll
                for (int s = 0; s < NSETS; s++)
#pragma unroll
                    for (int nt = 0; nt < 4; nt++)
                        bfr[s][nt] = lds128(sm + bbase[s][nt] + tkpoff);
            }
#pragma unroll
            for (int mt = 0; mt < MT; mt++) {
                uint4 af = lds128(sm + abase[mt] + (uint32_t)(ks * 512));
#pragma unroll
                for (int s = 0; s < NSETS; s++)
#pragma unroll
                    for (int nt = 0; nt < 4; nt++) {
                        uint32_t b0 = (ks & 1) ? bfr[s][nt].z : bfr[s][nt].x;
                        uint32_t b1 = (ks & 1) ? bfr[s][nt].w : bfr[s][nt].y;
                        mma_fp16(acc[s][mt][nt], af.x, af.y, af.z, af.w, b0, b1);
                    }
            }
        }
        sb += STG;
        if (sb >= 3 * STG) sb = 0;
    }

    // ---------- epilogue ----------
    if (IS1) {
        uint4* blob = d_ap + ((size_t)(e * 16 + blockIdx.x) * NI2 + blockIdx.y) * 1024;
#pragma unroll
        for (int mt = 0; mt < MT; mt++) {
            int mlo = mw * 32 + mt * 16 + g;
            float wlo = d_slot_w[seg + min(m0 + mlo,     cnt - 1)];
            float whi = d_slot_w[seg + min(m0 + mlo + 8, cnt - 1)];
#pragma unroll
            for (int tb = 0; tb < 2; tb++) {
                int na = tb * 2, nb2 = tb * 2 + 1;
                float l0 = silu(acc[0][mt][na ][0]) * acc[1][mt][na ][0] * wlo;
                float l1 = silu(acc[0][mt][na ][1]) * acc[1][mt][na ][1] * wlo;
                float h0 = silu(acc[0][mt][na ][2]) * acc[1][mt][na ][2] * whi;
                float h1 = silu(acc[0][mt][na ][3]) * acc[1][mt][na ][3] * whi;
                float l2 = silu(acc[0][mt][nb2][0]) * acc[1][mt][nb2][0] * wlo;
                float l3 = silu(acc[0][mt][nb2][1]) * acc[1][mt][nb2][1] * wlo;
                float h2 = silu(acc[0][mt][nb2][2]) * acc[1][mt][nb2][2] * whi;
                float h3 = silu(acc[0][mt][nb2][3]) * acc[1][mt][nb2][3] * whi;
                int grp = (mw * 2 + mt) * 4 + 2 * nw + tb;
                blob[grp * 32 + lane] = make_uint4(pk2(l0, l1), pk2(h0, h1),
                                                   pk2(l2, l3), pk2(h2, h3));
            }
        }
    } else {
        int n0 = blockIdx.y * 128 + nw * 32;
#pragma unroll
        for (int mt = 0; mt < MT; mt++) {
#pragma unroll
            for (int rs = 0; rs < 2; rs++) {
                int m = m0 + mw * 64 + mt * 16 + g + rs * 8;
                if (m < cnt) {
                    int tok = d_slot_token[seg + m];
                    float* row = out + (size_t)tok * H + n0;
#pragma unroll
                    for (int nt = 0; nt < 4; nt++)
                        red2(&row[nt * 8 + 2 * tig],
                             acc[0][mt][nt][rs * 2 + 0],
                             acc[0][mt][nt][rs * 2 + 1]);
                }
            }
        }
    }
}

// ===================== launch =====================
extern "C" void kernel_launch(void* const* d_in, const int* in_sizes, int n_in,
                              void* d_out, int out_size)
{
    const float* x   = (const float*)d_in[0];   // [2,1024,1024]
    const float* gw  = (const float*)d_in[1];   // [8,1024]
    const float* wgu = (const float*)d_in[2];   // [8,1024,7168]
    const float* wdn = (const float*)d_in[3];   // [8,3584,1024]
    float* out = (float*)d_out;

    int write_logits = (out_size >= T * H + T * NE) ? 1 : 0;
    float* logits = out + (size_t)T * H;

    cudaFuncSetAttribute(moe_gemm_mma<true>,
                         cudaFuncAttributeMaxDynamicSharedMemorySize, SMEMSZ);
    cudaFuncSetAttribute(moe_gemm_mma<false>,
                         cudaFuncAttributeMaxDynamicSharedMemorySize, SMEMSZ);

    // R13/R15 fork/join shape (measured best).
    cudaStream_t side;
    cudaStreamCreateWithFlags(&side, cudaStreamNonBlocking);
    cudaEvent_t evFork, evW1, evW2;
    cudaEventCreateWithFlags(&evFork, cudaEventDisableTiming);
    cudaEventCreateWithFlags(&evW1,   cudaEventDisableTiming);
    cudaEventCreateWithFlags(&evW2,   cudaEventDisableTiming);

    cudaEventRecord(evFork, 0);
    cudaStreamWaitEvent(side, evFork, 0);

    // side branch: weight packs + out zeroing
    pack_w_kernel<true><<<dim3(NI1, NT1, NE), 256, 0, side>>>(wgu);
    cudaEventRecord(evW1, side);
    zero_out_kernel<<<(T * H / 4 + 255) / 256, 256, 0, side>>>(out);
    pack_w_kernel<false><<<dim3(NI2, NT2, NE), 256, 0, side>>>(wdn);
    cudaEventRecord(evW2, side);

    // main branch: routing chain (scatter inlined in router)
    zero_counts_kernel<<<1, 32>>>();
    router_kernel<<<(T * 32 + 255) / 256, 256>>>(x, gw, logits, write_logits);
    pack_x_kernel<<<dim3(NI1, 16, NE), 256>>>(x);

    cudaStreamWaitEvent(0, evW1, 0);
    moe_gemm_mma<true><<<dim3(16, NT1, NE), 256, SMEMSZ>>>(nullptr);   // (16, 56, 8)
    cudaStreamWaitEvent(0, evW2, 0);
    moe_gemm_mma<false><<<dim3(16, NT2, NE), 256, SMEMSZ>>>(out);      // (16, 8, 8)
}